// round 16
// baseline (speedup 1.0000x reference)
#include <cuda_runtime.h>
#include <cuda_fp16.h>
#include <cstdint>

// out[b,o,t,n] = relu( sum_{i,k,m} theta[i,o,k] x[b,i,t,m] G[k,n,m] + bias[o] + x[b,o,t,n] )
// B=8, C=64, T=12, N=4096, KS=3. r' = bt*64+o in [0,6144). K_total = 3*4096 = 12288 (192 chunks of 64).
// All tensor math via mma.sync (HMMA) -- tcgen05 unavailable (PTX target compute_103, no 'a').

#define KCH 192

// A tiles (Z): [mt 48][kc 192][128 rows x 64 halfs], SW128-swizzled rows. 151 MB.
__device__ __align__(1024) __half g_zx[(size_t)48 * KCH * 8192];
// B tiles (G): [nt 16][kc 192][256 rows x 64 halfs], SW128-swizzled rows. 96 MB.
// (GEMM treats it as 32 half-strips of 128 rows: nt2 = n>>7.)
__device__ __align__(1024) __half g_bas[(size_t)16 * KCH * 16384];
// theta A-tile image: 192 rows x 64 halfs, SW128-swizzled. 24 KB.
__device__ __align__(1024) __half g_tha[192 * 64];

__device__ __forceinline__ uint32_t smem_u32(const void* p) {
    uint32_t a;
    asm("{ .reg .u64 t; cvta.to.shared.u64 t, %1; cvt.u32.u64 %0, t; }" : "=r"(a) : "l"(p));
    return a;
}
#define SWZ(x) ((x) ^ (((x) >> 3) & 0x70u))

#define MBAR_INIT(mb, c) asm volatile("mbarrier.init.shared.b64 [%0], %1;" :: "r"((uint32_t)(mb)), "r"((uint32_t)(c)) : "memory")
#define MBAR_ARRIVE(mb)  asm volatile("mbarrier.arrive.shared.b64 _, [%0];" :: "r"((uint32_t)(mb)) : "memory")
#define MBAR_EXTX(mb, by) asm volatile("mbarrier.arrive.expect_tx.shared.b64 _, [%0], %1;" :: "r"((uint32_t)(mb)), "r"((uint32_t)(by)) : "memory")
#define MBAR_WAIT(mb, ph) do { \
    asm volatile("{\n\t.reg .pred P;\n\tWL%=:\n\t" \
        "mbarrier.try_wait.parity.acquire.cta.shared::cta.b64 P, [%0], %1, 0x989680;\n\t" \
        "@P bra.uni WD%=;\n\tbra.uni WL%=;\n\tWD%=:\n\t}" :: "r"((uint32_t)(mb)), "r"((uint32_t)(ph)) : "memory"); \
} while (0)
#define FENCE_ASYNC() asm volatile("fence.proxy.async.shared::cta;" ::: "memory")

__device__ __forceinline__ void bulk_g2s(uint32_t dst, const void* src, uint32_t bytes, uint32_t mbar) {
    asm volatile("cp.async.bulk.shared::cluster.global.mbarrier::complete_tx::bytes [%0], [%1], %2, [%3];"
                 :: "r"(dst), "l"(src), "r"(bytes), "r"(mbar) : "memory");
}
__device__ __forceinline__ void bulk_s2g(void* dst, uint32_t src, uint32_t bytes) {
    asm volatile("cp.async.bulk.global.shared::cta.bulk_group [%0], [%1], %2;"
                 :: "l"(dst), "r"(src), "r"(bytes) : "memory");
}

#define LDSM_X4(r0, r1, r2, r3, addr) \
    asm volatile("ldmatrix.sync.aligned.m8n8.x4.shared.b16 {%0,%1,%2,%3}, [%4];" \
                 : "=r"(r0), "=r"(r1), "=r"(r2), "=r"(r3) : "r"(addr))

#define MMA16816(c, a, b0_, b1_) \
    asm volatile("mma.sync.aligned.m16n8k16.row.col.f32.f16.f16.f32 " \
                 "{%0,%1,%2,%3}, {%4,%5,%6,%7}, {%8,%9}, {%0,%1,%2,%3};" \
                 : "+f"((c)[0]), "+f"((c)[1]), "+f"((c)[2]), "+f"((c)[3]) \
                 : "r"((a)[0]), "r"((a)[1]), "r"((a)[2]), "r"((a)[3]), "r"(b0_), "r"(b1_))

// ---------------------------------------------------------------------------
// Pass 1a: G fp32 [k][n][m] -> fp16 pre-swizzled B tiles (standalone).
// ---------------------------------------------------------------------------
__global__ void __launch_bounds__(256) convert_kernel(const float* __restrict__ g) {
    size_t e = ((size_t)blockIdx.x * 256 + threadIdx.x) << 2;
    float4 v = *(const float4*)(g + e);
    uint32_t m = (uint32_t)(e & 4095), n = (uint32_t)((e >> 12) & 4095), k = (uint32_t)(e >> 24);
    uint32_t kc = (k << 6) + (m >> 6);
    uint32_t off = SWZ(((n & 255) << 7) + ((m & 63) << 1));
    __half2 h0 = __floats2half2_rn(v.x, v.y), h1 = __floats2half2_rn(v.z, v.w);
    uint2 w = make_uint2(*(uint32_t*)&h0, *(uint32_t*)&h1);
    *(uint2*)((char*)g_bas + (((size_t)((n >> 8) * KCH + kc)) << 15) + off) = w;
}

// ---------------------------------------------------------------------------
// Pass 1b: theta[i][o][k] -> A-tile image (rows k*64+o, col i, SW128). Tiny.
// ---------------------------------------------------------------------------
__global__ void __launch_bounds__(256) prep_theta_kernel(const float* __restrict__ th) {
    int e = blockIdx.x * 256 + threadIdx.x;          // 12288 elements, grid 48
    int k = e % 3, io = e / 3;
    int o = io & 63, i = io >> 6;
    *(__half*)((char*)g_tha + SWZ((uint32_t)(k * 64 + o) * 128 + (uint32_t)i * 2)) =
        __float2half_rn(th[e]);
}

// ---------------------------------------------------------------------------
// Pass 2: theta-mix. CTA = (bt, 128-wide m chunk). 256 threads, 8 warps (2M x 4N).
// Epilogue stages Z in smem and emits 8KB bulk shared->global stores (full-line
// writes; replaces 50%-efficient scattered 4B stores).
// ---------------------------------------------------------------------------
#define MX_A 1024
#define MX_B (1024 + 24576)
#define MX_SMEM (1024 + 24576 + 16384)

__global__ void __launch_bounds__(256) mix_kernel(const float* __restrict__ x) {
    extern __shared__ char smem[];
    uint32_t sb = smem_u32(smem);
    int tid = threadIdx.x, lane = tid & 31, wid = tid >> 5;
    int wm = wid >> 2, wn = wid & 3;
    int bt = blockIdx.x, m0 = blockIdx.y << 7;
    int b = bt / 12, t = bt - 12 * b;

    if (tid == 0) MBAR_INIT(sb + 64, 1);
    FENCE_ASYNC();
    __syncthreads();
    if (tid == 0) {                               // theta tile: one bulk copy
        MBAR_EXTX(sb + 64, 24576);
        bulk_g2s(sb + MX_A, g_tha, 24576, sb + 64);
    }

    const float* xb = x + ((size_t)b * 768 + t) * 4096 + m0;
#pragma unroll
    for (int it = 0; it < 4; it++) {
        int idx = tid + it * 256;
        int m = idx & 127, gq = idx >> 7;
        float v[8];
#pragma unroll
        for (int di = 0; di < 8; di++)
            v[di] = xb[(size_t)(gq * 8 + di) * 49152 + m];
        __half2 h0 = __floats2half2_rn(v[0], v[1]);
        __half2 h1 = __floats2half2_rn(v[2], v[3]);
        __half2 h2 = __floats2half2_rn(v[4], v[5]);
        __half2 h3 = __floats2half2_rn(v[6], v[7]);
        uint4 w = make_uint4(*(uint32_t*)&h0, *(uint32_t*)&h1,
                             *(uint32_t*)&h2, *(uint32_t*)&h3);
        *(uint4*)(smem + MX_B + SWZ((uint32_t)m * 128 + (uint32_t)gq * 16)) = w;
    }
    __syncthreads();
    MBAR_WAIT(sb + 64, 0);

    float c[6][4][4];
#pragma unroll
    for (int mi = 0; mi < 6; mi++)
#pragma unroll
        for (int ni = 0; ni < 4; ni++)
#pragma unroll
            for (int q = 0; q < 4; q++) c[mi][ni][q] = 0.f;

    uint32_t lrow = lane & 15, lcg = (uint32_t)(lane >> 4) << 4;
#pragma unroll
    for (int ks = 0; ks < 4; ks++) {
        uint32_t colb = (uint32_t)ks * 32 + lcg;
        uint32_t a[6][4], bf[2][4];
#pragma unroll
        for (int mi = 0; mi < 6; mi++) {
            uint32_t ad = sb + MX_A + SWZ((uint32_t)(wm * 96 + mi * 16 + lrow) * 128 + colb);
            LDSM_X4(a[mi][0], a[mi][1], a[mi][2], a[mi][3], ad);
        }
#pragma unroll
        for (int nj = 0; nj < 2; nj++) {
            uint32_t ad = sb + MX_B + SWZ((uint32_t)(wn * 32 + nj * 16 + lrow) * 128 + colb);
            LDSM_X4(bf[nj][0], bf[nj][1], bf[nj][2], bf[nj][3], ad);
        }
#pragma unroll
        for (int mi = 0; mi < 6; mi++)
#pragma unroll
            for (int ni = 0; ni < 4; ni++)
                MMA16816(c[mi][ni], a[mi], bf[ni >> 1][ni & 1], bf[ni >> 1][(ni & 1) + 2]);
    }

    // epilogue: stage Z in smem (reuse A/B region), bulk 8KB stores.
    // Tile block for (k, j): rows rbase..rbase+63 of tile (mt, kc) = contiguous
    // 8KB; rbase % 8 == 0 so the SW128 xor depends only on local row o&7.
    __syncthreads();                              // all LDSM reads of A/B done
    char* gz = (char*)g_zx;
    uint32_t mt = (uint32_t)(bt >> 1);
    uint32_t rbase = (uint32_t)(bt & 1) << 6;
#pragma unroll 1
    for (int rnd = 0; rnd < 2; rnd++) {           // 2 rounds x 3 blocks x 8KB
#pragma unroll
        for (int mi = 0; mi < 6; mi++) {
#pragma unroll
            for (int h = 0; h < 2; h++) {
                uint32_t ko = (uint32_t)(wm * 96 + mi * 16 + h * 8) + (uint32_t)(lane >> 2);
                uint32_t k = ko >> 6, o = ko & 63;
#pragma unroll
                for (int ni = 0; ni < 4; ni++) {
                    uint32_t mloc = (uint32_t)(wn * 32 + ni * 8) + (uint32_t)((lane & 3) << 1);
                    int q = (int)(k * 2 + (mloc >> 6));
                    if (q >= rnd * 3 && q < rnd * 3 + 3) {
                        __half2 hv = __floats2half2_rn(c[mi][ni][2 * h], c[mi][ni][2 * h + 1]);
                        *(uint32_t*)(smem + 1024 + (q - rnd * 3) * 8192 +
                                     SWZ(o * 128 + ((mloc & 63) << 1))) = *(uint32_t*)&hv;
                    }
                }
            }
        }
        __syncthreads();
        if (tid == 0) {
            FENCE_ASYNC();
#pragma unroll
            for (int qq = 0; qq < 3; qq++) {
                int q = rnd * 3 + qq;
                uint32_t kc = (uint32_t)(q >> 1) * 64 + (uint32_t)(m0 >> 6) + (q & 1);
                bulk_s2g(gz + (((size_t)(mt * KCH + kc)) << 14) + ((size_t)rbase << 7),
                         sb + 1024 + qq * 8192, 8192);
            }
            asm volatile("cp.async.bulk.commit_group;" ::: "memory");
            asm volatile("cp.async.bulk.wait_group 0;" ::: "memory");
        }
        __syncthreads();
    }
}

// ---------------------------------------------------------------------------
// Pass 3: GEMM -- BM=128 BN=128 BK=64, 3 stages (32KB), 8 consumer warps
// (32x64 warp tile) + 1 producer, 2 CTAs/SM. Chunk loop unrolled by 3 so all
// stage indices / mbarrier addresses / parities are compile-time constants.
// ---------------------------------------------------------------------------
#define G2_STG 32768
#define G2_NS 3
#define G2_SMEM (1024 + G2_NS * G2_STG)

__global__ void __launch_bounds__(288, 2) gemm_kernel(const float* __restrict__ x,
                                                      const float* __restrict__ bias,
                                                      float* __restrict__ out) {
    extern __shared__ char smem[];
    uint32_t sb = smem_u32(smem);
    int tid = threadIdx.x, lane = tid & 31, wid = tid >> 5;
    int id = blockIdx.x;
    // grouped raster: 6 groups of (8 mt x 32 nt2) = 256 CTAs
    int mt = (id >> 8) * 8 + (id & 7);      // 48 mtiles
    int nt2 = (id >> 3) & 31;               // 32 ntiles of 128 cols

    if (tid == 0) {
#pragma unroll
        for (int s = 0; s < G2_NS; s++) {
            MBAR_INIT(sb + 16 * s, 1);       // full (tx-based)
            MBAR_INIT(sb + 16 * s + 8, 8);   // empty (8 consumer warps)
        }
    }
    FENCE_ASYNC();
    __syncthreads();

    if (wid == 8) {                          // producer warp
        if (lane == 0) {
            const char* As = (const char*)g_zx + ((size_t)mt * KCH << 14);
            const char* Bs = (const char*)g_bas + ((size_t)(nt2 >> 1) * KCH << 15)
                             + ((size_t)(nt2 & 1) << 14);
            int s = 0, rnd = 0;
            for (int cc = 0; cc < KCH; cc++) {
                if (cc >= G2_NS) MBAR_WAIT(sb + 16 * s + 8, (rnd + 1) & 1);
                MBAR_EXTX(sb + 16 * s, G2_STG);
                uint32_t dst = sb + 1024 + s * G2_STG;
                bulk_g2s(dst, As + ((size_t)cc << 14), 16384, sb + 16 * s);
                bulk_g2s(dst + 16384, Bs + ((size_t)cc << 15), 16384, sb + 16 * s);
                if (++s == G2_NS) { s = 0; rnd ^= 1; }
            }
        }
        return;
    }

    // 8 consumer warps: 4 (wm) x 2 (wn), warp tile 32 rows x 64 cols
    int wm = wid >> 1, wn = wid & 1;
    uint32_t lrow = lane & 15, lcg = (uint32_t)(lane >> 4) << 4;
    uint32_t aoff[2], boff[4];
#pragma unroll
    for (int mi = 0; mi < 2; mi++)
        aoff[mi] = (uint32_t)(wm * 32 + mi * 16 + lrow) * 128;
#pragma unroll
    for (int nj = 0; nj < 4; nj++)
        boff[nj] = 16384u + (uint32_t)(wn * 64 + nj * 16 + lrow) * 128;
    uint32_t swa = ((lrow & 7) << 4);

    float c[2][8][4];
#pragma unroll
    for (int mi = 0; mi < 2; mi++)
#pragma unroll
        for (int ni = 0; ni < 8; ni++)
#pragma unroll
            for (int q = 0; q < 4; q++) c[mi][ni][q] = 0.f;

    // one chunk with compile-time stage S and parity PH
#define CHUNK_BODY(S, PH) do { \
    MBAR_WAIT(sb + 16 * (S), (PH)); \
    const uint32_t stg = sb + 1024 + (S) * G2_STG; \
    _Pragma("unroll") \
    for (int ks = 0; ks < 4; ks++) { \
        uint32_t colb = ((uint32_t)ks * 32 + lcg) ^ swa; \
        uint32_t a[2][4], bf[4][4]; \
        _Pragma("unroll") \
        for (int mi = 0; mi < 2; mi++) \
            LDSM_X4(a[mi][0], a[mi][1], a[mi][2], a[mi][3], stg + aoff[mi] + colb); \
        _Pragma("unroll") \
        for (int nj = 0; nj < 4; nj++) \
            LDSM_X4(bf[nj][0], bf[nj][1], bf[nj][2], bf[nj][3], stg + boff[nj] + colb); \
        if (ks == 3 && lane == 0) MBAR_ARRIVE(sb + 16 * (S) + 8); \
        _Pragma("unroll") \
        for (int mi = 0; mi < 2; mi++) \
            _Pragma("unroll") \
            for (int ni = 0; ni < 8; ni++) \
                MMA16816(c[mi][ni], a[mi], bf[ni >> 1][ni & 1], bf[ni >> 1][(ni & 1) + 2]); \
    } \
} while (0)

#pragma unroll 1
    for (int trip = 0; trip < KCH / (2 * G2_NS); trip++) {   // 32 trips x 6 chunks
        CHUNK_BODY(0, 0); CHUNK_BODY(1, 0); CHUNK_BODY(2, 0);
        CHUNK_BODY(0, 1); CHUNK_BODY(1, 1); CHUNK_BODY(2, 1);
    }
#undef CHUNK_BODY

    // fused epilogue: bias + identity residual + relu
#pragma unroll
    for (int mi = 0; mi < 2; mi++) {
#pragma unroll
        for (int h = 0; h < 2; h++) {
            uint32_t r = (uint32_t)(mt * 128 + wm * 32 + mi * 16 + h * 8) + (uint32_t)(lane >> 2);
            uint32_t bt = r >> 6, o = r & 63;
            uint32_t bb = bt / 12, tt = bt - 12 * bb;
            size_t base = ((size_t)((bb << 6) + o) * 12 + tt) * 4096;
            float bv = __ldg(bias + o);
#pragma unroll
            for (int ni = 0; ni < 8; ni++) {
                size_t col = (size_t)(nt2 * 128 + wn * 64 + ni * 8) + ((lane & 3) << 1);
                float2 xv = *(const float2*)(x + base + col);
                float2 ov;
                ov.x = fmaxf(c[mi][ni][2 * h + 0] + bv + xv.x, 0.f);
                ov.y = fmaxf(c[mi][ni][2 * h + 1] + bv + xv.y, 0.f);
                *(float2*)(out + base + col) = ov;
            }
        }
    }
}

// ---------------------------------------------------------------------------
extern "C" void kernel_launch(void* const* d_in, const int* in_sizes, int n_in,
                              void* d_out, int out_size) {
    const float* x = (const float*)d_in[0];
    const float* g = (const float*)d_in[1];
    const float* th = (const float*)d_in[2];
    const float* bias = (const float*)d_in[3];
    float* out = (float*)d_out;

    static cudaStream_t s2 = nullptr;
    static cudaEvent_t ev_fork = nullptr, ev_join = nullptr;
    if (s2 == nullptr) {
        cudaStreamCreateWithFlags(&s2, cudaStreamNonBlocking);
        cudaEventCreateWithFlags(&ev_fork, cudaEventDisableTiming);
        cudaEventCreateWithFlags(&ev_join, cudaEventDisableTiming);
        cudaFuncSetAttribute(gemm_kernel, cudaFuncAttributeMaxDynamicSharedMemorySize, G2_SMEM);
    }

    cudaEventRecord(ev_fork, 0);
    cudaStreamWaitEvent(s2, ev_fork, 0);
    convert_kernel<<<49152, 256, 0, s2>>>(g);
    prep_theta_kernel<<<48, 256>>>(th);
    mix_kernel<<<dim3(96, 32), 256, MX_SMEM>>>(x);
    cudaEventRecord(ev_join, s2);
    cudaStreamWaitEvent(0, ev_join, 0);

    gemm_kernel<<<1536, 288, G2_SMEM>>>(x, bias, out);
}

// round 17
// speedup vs baseline: 1.0132x; 1.0132x over previous
#include <cuda_runtime.h>
#include <cuda_fp16.h>
#include <cstdint>

// out[b,o,t,n] = relu( sum_{i,k,m} theta[i,o,k] x[b,i,t,m] G[k,n,m] + bias[o] + x[b,o,t,n] )
// B=8, C=64, T=12, N=4096, KS=3. r' = bt*64+o in [0,6144). K_total = 3*4096 = 12288 (192 chunks of 64).
// All tensor math via mma.sync (HMMA) -- tcgen05 unavailable (PTX target compute_103, no 'a').

#define KCH 192

// A tiles (Z): [mt 48][kc 192][128 rows x 64 halfs], SW128-swizzled rows. 151 MB.
// (GEMM v3 treats it as 96 half-tiles of 64 rows: mt64 = r>>6.)
__device__ __align__(1024) __half g_zx[(size_t)48 * KCH * 8192];
// B tiles (G): [nt 16][kc 192][256 rows x 64 halfs], SW128-swizzled rows. 96 MB.
// (GEMM treats it as 32 half-strips of 128 rows: nt2 = n>>7.)
__device__ __align__(1024) __half g_bas[(size_t)16 * KCH * 16384];
// theta A-tile image: 192 rows x 64 halfs, SW128-swizzled. 24 KB.
__device__ __align__(1024) __half g_tha[192 * 64];

__device__ __forceinline__ uint32_t smem_u32(const void* p) {
    uint32_t a;
    asm("{ .reg .u64 t; cvta.to.shared.u64 t, %1; cvt.u32.u64 %0, t; }" : "=r"(a) : "l"(p));
    return a;
}
#define SWZ(x) ((x) ^ (((x) >> 3) & 0x70u))

#define MBAR_INIT(mb, c) asm volatile("mbarrier.init.shared.b64 [%0], %1;" :: "r"((uint32_t)(mb)), "r"((uint32_t)(c)) : "memory")
#define MBAR_ARRIVE(mb)  asm volatile("mbarrier.arrive.shared.b64 _, [%0];" :: "r"((uint32_t)(mb)) : "memory")
#define MBAR_EXTX(mb, by) asm volatile("mbarrier.arrive.expect_tx.shared.b64 _, [%0], %1;" :: "r"((uint32_t)(mb)), "r"((uint32_t)(by)) : "memory")
#define MBAR_WAIT(mb, ph) do { \
    asm volatile("{\n\t.reg .pred P;\n\tWL%=:\n\t" \
        "mbarrier.try_wait.parity.acquire.cta.shared::cta.b64 P, [%0], %1, 0x989680;\n\t" \
        "@P bra.uni WD%=;\n\tbra.uni WL%=;\n\tWD%=:\n\t}" :: "r"((uint32_t)(mb)), "r"((uint32_t)(ph)) : "memory"); \
} while (0)
#define FENCE_ASYNC() asm volatile("fence.proxy.async.shared::cta;" ::: "memory")

__device__ __forceinline__ void bulk_g2s(uint32_t dst, const void* src, uint32_t bytes, uint32_t mbar) {
    asm volatile("cp.async.bulk.shared::cluster.global.mbarrier::complete_tx::bytes [%0], [%1], %2, [%3];"
                 :: "r"(dst), "l"(src), "r"(bytes), "r"(mbar) : "memory");
}

#define LDSM_X4(r0, r1, r2, r3, addr) \
    asm volatile("ldmatrix.sync.aligned.m8n8.x4.shared.b16 {%0,%1,%2,%3}, [%4];" \
                 : "=r"(r0), "=r"(r1), "=r"(r2), "=r"(r3) : "r"(addr))

#define MMA16816(c, a, b0_, b1_) \
    asm volatile("mma.sync.aligned.m16n8k16.row.col.f32.f16.f16.f32 " \
                 "{%0,%1,%2,%3}, {%4,%5,%6,%7}, {%8,%9}, {%0,%1,%2,%3};" \
                 : "+f"((c)[0]), "+f"((c)[1]), "+f"((c)[2]), "+f"((c)[3]) \
                 : "r"((a)[0]), "r"((a)[1]), "r"((a)[2]), "r"((a)[3]), "r"(b0_), "r"(b1_))

// ---------------------------------------------------------------------------
// Pass 1a: G fp32 [k][n][m] -> fp16 pre-swizzled B tiles (standalone).
// ---------------------------------------------------------------------------
__global__ void __launch_bounds__(256) convert_kernel(const float* __restrict__ g) {
    size_t e = ((size_t)blockIdx.x * 256 + threadIdx.x) << 2;
    float4 v = *(const float4*)(g + e);
    uint32_t m = (uint32_t)(e & 4095), n = (uint32_t)((e >> 12) & 4095), k = (uint32_t)(e >> 24);
    uint32_t kc = (k << 6) + (m >> 6);
    uint32_t off = SWZ(((n & 255) << 7) + ((m & 63) << 1));
    __half2 h0 = __floats2half2_rn(v.x, v.y), h1 = __floats2half2_rn(v.z, v.w);
    uint2 w = make_uint2(*(uint32_t*)&h0, *(uint32_t*)&h1);
    *(uint2*)((char*)g_bas + (((size_t)((n >> 8) * KCH + kc)) << 15) + off) = w;
}

// ---------------------------------------------------------------------------
// Pass 1b: theta[i][o][k] -> A-tile image (rows k*64+o, col i, SW128). Tiny.
// ---------------------------------------------------------------------------
__global__ void __launch_bounds__(256) prep_theta_kernel(const float* __restrict__ th) {
    int e = blockIdx.x * 256 + threadIdx.x;          // 12288 elements, grid 48
    int k = e % 3, io = e / 3;
    int o = io & 63, i = io >> 6;
    *(__half*)((char*)g_tha + SWZ((uint32_t)(k * 64 + o) * 128 + (uint32_t)i * 2)) =
        __float2half_rn(th[e]);
}

// ---------------------------------------------------------------------------
// Pass 2: theta-mix (round-15 version -- bulk-store epilogue regressed).
// CTA = (bt, 128-wide m chunk). 256 threads, 8 warps (2M x 4N).
// ---------------------------------------------------------------------------
#define MX_A 1024
#define MX_B (1024 + 24576)
#define MX_SMEM (1024 + 24576 + 16384)

__global__ void __launch_bounds__(256) mix_kernel(const float* __restrict__ x) {
    extern __shared__ char smem[];
    uint32_t sb = smem_u32(smem);
    int tid = threadIdx.x, lane = tid & 31, wid = tid >> 5;
    int wm = wid >> 2, wn = wid & 3;
    int bt = blockIdx.x, m0 = blockIdx.y << 7;
    int b = bt / 12, t = bt - 12 * b;

    if (tid == 0) MBAR_INIT(sb + 64, 1);
    FENCE_ASYNC();
    __syncthreads();
    if (tid == 0) {                               // theta tile: one bulk copy
        MBAR_EXTX(sb + 64, 24576);
        bulk_g2s(sb + MX_A, g_tha, 24576, sb + 64);
    }

    const float* xb = x + ((size_t)b * 768 + t) * 4096 + m0;
#pragma unroll
    for (int it = 0; it < 4; it++) {
        int idx = tid + it * 256;
        int m = idx & 127, gq = idx >> 7;
        float v[8];
#pragma unroll
        for (int di = 0; di < 8; di++)
            v[di] = xb[(size_t)(gq * 8 + di) * 49152 + m];
        __half2 h0 = __floats2half2_rn(v[0], v[1]);
        __half2 h1 = __floats2half2_rn(v[2], v[3]);
        __half2 h2 = __floats2half2_rn(v[4], v[5]);
        __half2 h3 = __floats2half2_rn(v[6], v[7]);
        uint4 w = make_uint4(*(uint32_t*)&h0, *(uint32_t*)&h1,
                             *(uint32_t*)&h2, *(uint32_t*)&h3);
        *(uint4*)(smem + MX_B + SWZ((uint32_t)m * 128 + (uint32_t)gq * 16)) = w;
    }
    __syncthreads();
    MBAR_WAIT(sb + 64, 0);

    float c[6][4][4];
#pragma unroll
    for (int mi = 0; mi < 6; mi++)
#pragma unroll
        for (int ni = 0; ni < 4; ni++)
#pragma unroll
            for (int q = 0; q < 4; q++) c[mi][ni][q] = 0.f;

    uint32_t lrow = lane & 15, lcg = (uint32_t)(lane >> 4) << 4;
#pragma unroll
    for (int ks = 0; ks < 4; ks++) {
        uint32_t colb = (uint32_t)ks * 32 + lcg;
        uint32_t a[6][4], bf[2][4];
#pragma unroll
        for (int mi = 0; mi < 6; mi++) {
            uint32_t ad = sb + MX_A + SWZ((uint32_t)(wm * 96 + mi * 16 + lrow) * 128 + colb);
            LDSM_X4(a[mi][0], a[mi][1], a[mi][2], a[mi][3], ad);
        }
#pragma unroll
        for (int nj = 0; nj < 2; nj++) {
            uint32_t ad = sb + MX_B + SWZ((uint32_t)(wn * 32 + nj * 16 + lrow) * 128 + colb);
            LDSM_X4(bf[nj][0], bf[nj][1], bf[nj][2], bf[nj][3], ad);
        }
#pragma unroll
        for (int mi = 0; mi < 6; mi++)
#pragma unroll
            for (int ni = 0; ni < 4; ni++)
                MMA16816(c[mi][ni], a[mi], bf[ni >> 1][ni & 1], bf[ni >> 1][(ni & 1) + 2]);
    }

    char* gz = (char*)g_zx;
    uint32_t mt = (uint32_t)(bt >> 1);
    uint32_t rbase = (uint32_t)(bt & 1) << 6;
#pragma unroll
    for (int mi = 0; mi < 6; mi++) {
#pragma unroll
        for (int h = 0; h < 2; h++) {
            uint32_t ko = (uint32_t)(wm * 96 + mi * 16 + h * 8) + (uint32_t)(lane >> 2);
            uint32_t k = ko >> 6, o = ko & 63;
            uint32_t row = rbase + o;
#pragma unroll
            for (int ni = 0; ni < 4; ni++) {
                uint32_t m = (uint32_t)(m0 + wn * 32 + ni * 8) + (uint32_t)((lane & 3) << 1);
                uint32_t kc = k * 64 + (m >> 6);
                __half2 hv = __floats2half2_rn(c[mi][ni][2 * h], c[mi][ni][2 * h + 1]);
                *(uint32_t*)(gz + (((size_t)(mt * KCH + kc)) << 14) +
                             SWZ(row * 128 + ((m & 63) << 1))) = *(uint32_t*)&hv;
            }
        }
    }
}

// ---------------------------------------------------------------------------
// Pass 3: GEMM v3 -- BM=64 BN=128 BK=64, 3 stages (24KB), 4 consumer warps
// (32x64 warp tile, identical inner loop to the round-15 winner) + 1 producer.
// 160 threads, 73KB smem -> 3 CTAs/SM (444 slots): 3072 jobs / 444 = 6.92
// waves, tail waste ~1% (was 16% at 1536 jobs / 296 slots).
// ---------------------------------------------------------------------------
#define G3_STG 24576
#define G3_NS 3
#define G3_SMEM (1024 + G3_NS * G3_STG)

__global__ void __launch_bounds__(160, 3) gemm_kernel(const float* __restrict__ x,
                                                      const float* __restrict__ bias,
                                                      float* __restrict__ out) {
    extern __shared__ char smem[];
    uint32_t sb = smem_u32(smem);
    int tid = threadIdx.x, lane = tid & 31, wid = tid >> 5;
    int id = blockIdx.x;
    // grouped raster: 12 groups of (8 mt64 x 32 nt2) = 256 CTAs
    int mt64 = (id >> 8) * 8 + (id & 7);    // 96 mtiles of 64 rows
    int nt2 = (id >> 3) & 31;               // 32 ntiles of 128 cols

    if (tid == 0) {
#pragma unroll
        for (int s = 0; s < G3_NS; s++) {
            MBAR_INIT(sb + 16 * s, 1);       // full (tx-based)
            MBAR_INIT(sb + 16 * s + 8, 4);   // empty (4 consumer warps)
        }
    }
    FENCE_ASYNC();
    __syncthreads();

    if (wid == 4) {                          // producer warp
        if (lane == 0) {
            const char* As = (const char*)g_zx + ((size_t)(mt64 >> 1) * KCH << 14)
                             + ((size_t)(mt64 & 1) << 13);
            const char* Bs = (const char*)g_bas + ((size_t)(nt2 >> 1) * KCH << 15)
                             + ((size_t)(nt2 & 1) << 14);
            int s = 0, rnd = 0;
            for (int cc = 0; cc < KCH; cc++) {
                if (cc >= G3_NS) MBAR_WAIT(sb + 16 * s + 8, (rnd + 1) & 1);
                MBAR_EXTX(sb + 16 * s, G3_STG);
                uint32_t dst = sb + 1024 + s * G3_STG;
                bulk_g2s(dst, As + ((size_t)cc << 14), 8192, sb + 16 * s);
                bulk_g2s(dst + 8192, Bs + ((size_t)cc << 15), 16384, sb + 16 * s);
                if (++s == G3_NS) { s = 0; rnd ^= 1; }
            }
        }
        return;
    }

    // 4 consumer warps: 2 (wm) x 2 (wn), warp tile 32 rows x 64 cols
    int wm = wid >> 1, wn = wid & 1;
    uint32_t lrow = lane & 15, lcg = (uint32_t)(lane >> 4) << 4;
    uint32_t aoff[2], boff[4];
#pragma unroll
    for (int mi = 0; mi < 2; mi++)
        aoff[mi] = (uint32_t)(wm * 32 + mi * 16 + lrow) * 128;
#pragma unroll
    for (int nj = 0; nj < 4; nj++)
        boff[nj] = 8192u + (uint32_t)(wn * 64 + nj * 16 + lrow) * 128;
    uint32_t swa = ((lrow & 7) << 4);

    float c[2][8][4];
#pragma unroll
    for (int mi = 0; mi < 2; mi++)
#pragma unroll
        for (int ni = 0; ni < 8; ni++)
#pragma unroll
            for (int q = 0; q < 4; q++) c[mi][ni][q] = 0.f;

    // one chunk with compile-time stage S and parity PH
#define CHUNK_BODY(S, PH) do { \
    MBAR_WAIT(sb + 16 * (S), (PH)); \
    const uint32_t stg = sb + 1024 + (S) * G3_STG; \
    _Pragma("unroll") \
    for (int ks = 0; ks < 4; ks++) { \
        uint32_t colb = ((uint32_t)ks * 32 + lcg) ^ swa; \
        uint32_t a[2][4], bf[4][4]; \
        _Pragma("unroll") \
        for (int mi = 0; mi < 2; mi++) \
            LDSM_X4(a[mi][0], a[mi][1], a[mi][2], a[mi][3], stg + aoff[mi] + colb); \
        _Pragma("unroll") \
        for (int nj = 0; nj < 4; nj++) \
            LDSM_X4(bf[nj][0], bf[nj][1], bf[nj][2], bf[nj][3], stg + boff[nj] + colb); \
        if (ks == 3 && lane == 0) MBAR_ARRIVE(sb + 16 * (S) + 8); \
        _Pragma("unroll") \
        for (int mi = 0; mi < 2; mi++) \
            _Pragma("unroll") \
            for (int ni = 0; ni < 8; ni++) \
                MMA16816(c[mi][ni], a[mi], bf[ni >> 1][ni & 1], bf[ni >> 1][(ni & 1) + 2]); \
    } \
} while (0)

#pragma unroll 1
    for (int trip = 0; trip < KCH / (2 * G3_NS); trip++) {   // 32 trips x 6 chunks
        CHUNK_BODY(0, 0); CHUNK_BODY(1, 0); CHUNK_BODY(2, 0);
        CHUNK_BODY(0, 1); CHUNK_BODY(1, 1); CHUNK_BODY(2, 1);
    }
#undef CHUNK_BODY

    // fused epilogue: bias + identity residual + relu
#pragma unroll
    for (int mi = 0; mi < 2; mi++) {
#pragma unroll
        for (int h = 0; h < 2; h++) {
            uint32_t r = (uint32_t)(mt64 * 64 + wm * 32 + mi * 16 + h * 8) + (uint32_t)(lane >> 2);
            uint32_t bt = r >> 6, o = r & 63;
            uint32_t bb = bt / 12, tt = bt - 12 * bb;
            size_t base = ((size_t)((bb << 6) + o) * 12 + tt) * 4096;
            float bv = __ldg(bias + o);
#pragma unroll
            for (int ni = 0; ni < 8; ni++) {
                size_t col = (size_t)(nt2 * 128 + wn * 64 + ni * 8) + ((lane & 3) << 1);
                float2 xv = *(const float2*)(x + base + col);
                float2 ov;
                ov.x = fmaxf(c[mi][ni][2 * h + 0] + bv + xv.x, 0.f);
                ov.y = fmaxf(c[mi][ni][2 * h + 1] + bv + xv.y, 0.f);
                *(float2*)(out + base + col) = ov;
            }
        }
    }
}

// ---------------------------------------------------------------------------
extern "C" void kernel_launch(void* const* d_in, const int* in_sizes, int n_in,
                              void* d_out, int out_size) {
    const float* x = (const float*)d_in[0];
    const float* g = (const float*)d_in[1];
    const float* th = (const float*)d_in[2];
    const float* bias = (const float*)d_in[3];
    float* out = (float*)d_out;

    static cudaStream_t s2 = nullptr;
    static cudaEvent_t ev_fork = nullptr, ev_join = nullptr;
    if (s2 == nullptr) {
        cudaStreamCreateWithFlags(&s2, cudaStreamNonBlocking);
        cudaEventCreateWithFlags(&ev_fork, cudaEventDisableTiming);
        cudaEventCreateWithFlags(&ev_join, cudaEventDisableTiming);
        cudaFuncSetAttribute(gemm_kernel, cudaFuncAttributeMaxDynamicSharedMemorySize, G3_SMEM);
    }

    cudaEventRecord(ev_fork, 0);
    cudaStreamWaitEvent(s2, ev_fork, 0);
    convert_kernel<<<49152, 256, 0, s2>>>(g);
    prep_theta_kernel<<<48, 256>>>(th);
    mix_kernel<<<dim3(96, 32), 256, MX_SMEM>>>(x);
    cudaEventRecord(ev_join, s2);
    cudaStreamWaitEvent(0, ev_join, 0);

    gemm_kernel<<<3072, 160, G3_SMEM>>>(x, bias, out);
}